// round 2
// baseline (speedup 1.0000x reference)
#include <cuda_runtime.h>
#include <cstdint>

#define HW 16384
#define NB 16
#define ASTRIDE 260   // 64 rows (o) x 260 (k stride), 260 % 32 == 4 -> conflict-free A frags
#define BSTRIDE 264   // 32 rows (k) x 264 (n stride), 264 % 32 == 8 -> conflict-free B frags

// Scratch (allocation-free rule: __device__ globals)
__device__ float g_fc[NB * 4 * 64];      // pooled means [b][k][c]
__device__ float g_M[NB * 64 * 256];     // per-batch fused matrix, tf32-rounded, [b][o][call]

__device__ __forceinline__ uint32_t f2tf(float f) {
    uint32_t r;
    asm("cvt.rna.tf32.f32 %0, %1;" : "=r"(r) : "f"(f));
    return r;
}

__device__ __forceinline__ void mma_tf32(float c[4],
                                         uint32_t a0, uint32_t a1, uint32_t a2, uint32_t a3,
                                         uint32_t b0, uint32_t b1) {
    asm volatile(
        "mma.sync.aligned.m16n8k8.row.col.f32.tf32.tf32.f32 "
        "{%0,%1,%2,%3},{%4,%5,%6,%7},{%8,%9},{%0,%1,%2,%3};"
        : "+f"(c[0]), "+f"(c[1]), "+f"(c[2]), "+f"(c[3])
        : "r"(a0), "r"(a1), "r"(a2), "r"(a3), "r"(b0), "r"(b1));
}

// ---------------------------------------------------------------------------
// Kernel 1: adaptive-avg-pool(1) of all four inputs. One CTA per (b,k,c) plane.
// ---------------------------------------------------------------------------
__global__ void k_pool(const float* __restrict__ low, const float* __restrict__ high,
                       const float* __restrict__ flw, const float* __restrict__ fbk) {
    int plane = blockIdx.x;          // 0..4095
    int b = plane >> 8;
    int k = (plane >> 6) & 3;
    int c = plane & 63;
    const float* src = (k == 0) ? low : (k == 1) ? high : (k == 2) ? flw : fbk;
    src += (size_t)(b * 64 + c) * HW;

    int t = threadIdx.x;
    float s = 0.f;
    const float4* src4 = (const float4*)src;
#pragma unroll
    for (int i = 0; i < 16; i++) {
        float4 v = src4[t + i * 256];
        s += (v.x + v.y) + (v.z + v.w);
    }
    __shared__ float red[8];
#pragma unroll
    for (int off = 16; off; off >>= 1) s += __shfl_down_sync(0xffffffffu, s, off);
    if ((t & 31) == 0) red[t >> 5] = s;
    __syncthreads();
    if (t < 8) {
        s = red[t];
        s += __shfl_down_sync(0xffu, s, 4);
        s += __shfl_down_sync(0xffu, s, 2);
        s += __shfl_down_sync(0xffu, s, 1);
        if (t == 0) g_fc[(b * 4 + k) * 64 + c] = s * (1.0f / HW);
    }
}

// ---------------------------------------------------------------------------
// Kernel 2: adjacency + GCN + SE heads + fused per-batch matrix M_b.
// One CTA (256 threads) per batch.
// ---------------------------------------------------------------------------
__global__ void k_prep(const float* __restrict__ Wgcn, const float* __restrict__ bgcn,
                       const float* __restrict__ W1, const float* __restrict__ b1,
                       const float* __restrict__ W2, const float* __restrict__ b2,
                       const float* __restrict__ W3, const float* __restrict__ b3,
                       const float* __restrict__ W4, const float* __restrict__ b4,
                       const float* __restrict__ Wgate) {
    int b = blockIdx.x;
    int t = threadIdx.x;
    __shared__ float fc_s[256];
    __shared__ float dot_s[16];
    __shared__ float adj_s[16];
    __shared__ float xw_s[256];
    __shared__ float h_s[256];
    __shared__ float e_s[256];

    fc_s[t] = g_fc[b * 256 + t];
    __syncthreads();

    if (t < 16) {                               // pairwise dots [4x4]
        int i = t >> 2, j = t & 3;
        float d = 0.f;
#pragma unroll
        for (int c = 0; c < 64; c++) d += fc_s[i * 64 + c] * fc_s[j * 64 + c];
        dot_s[t] = d;
    }
    __syncthreads();
    if (t < 16) {                               // cosine adjacency
        int i = t >> 2, j = t & 3;
        adj_s[t] = dot_s[t] / (sqrtf(dot_s[i * 4 + i]) * sqrtf(dot_s[j * 4 + j]));
    }
    __syncthreads();
    {                                           // xw = fc @ Wgcn  (4x64)
        int j = t >> 6, d = t & 63;
        float a = 0.f;
#pragma unroll 8
        for (int c = 0; c < 64; c++) a += fc_s[j * 64 + c] * Wgcn[c * 64 + d];
        xw_s[t] = a;
    }
    __syncthreads();
    {                                           // h = relu(adj @ xw + bgcn)
        int i = t >> 6, d = t & 63;
        float a = bgcn[d];
#pragma unroll
        for (int j = 0; j < 4; j++) a += adj_s[i * 4 + j] * xw_s[j * 64 + d];
        h_s[t] = fmaxf(a, 0.f);
    }
    __syncthreads();
    {                                           // e_k = sigmoid(feat @ Wk^T + bk)
        int k = t >> 6, j = t & 63;
        const float* Wk = (k == 0) ? W1 : (k == 1) ? W2 : (k == 2) ? W3 : W4;
        const float* bk = (k == 0) ? b1 : (k == 1) ? b2 : (k == 2) ? b3 : b4;
        float a = bk[j];
#pragma unroll 8
        for (int d = 0; d < 256; d++) a += h_s[d] * Wk[j * 256 + d];
        e_s[t] = 1.0f / (1.0f + expf(-a));
    }
    __syncthreads();
    // M_b[o, k*64+c] = Gk[o,c] + e_{k+1}[c] * (Gsum[o,c] - Gk[o,c]); round to tf32
#pragma unroll
    for (int i = 0; i < 64; i++) {
        int idx = t + i * 256;
        int o = idx >> 8, call = idx & 255;
        int k = call >> 6, c = call & 63;
        float gk = Wgate[idx];
        float gsum = Wgate[o * 256 + c] + Wgate[o * 256 + 64 + c] +
                     Wgate[o * 256 + 128 + c] + Wgate[o * 256 + 192 + c];
        float m = gk + e_s[k * 64 + c] * (gsum - gk);
        g_M[b * 16384 + idx] = __uint_as_float(f2tf(m));
    }
}

// ---------------------------------------------------------------------------
// Kernel 3: out[b,:,px_tile] = M_b @ X  via tf32 mma, + bgate.
// CTA = (batch, 256-pixel tile), 256 threads (8 warps).
// Each warp covers m=64 outputs x n=32 pixels (4 m16 tiles x 4 n8 frags).
// ---------------------------------------------------------------------------
__global__ void __launch_bounds__(256, 2)
k_main(const float* __restrict__ low, const float* __restrict__ high,
       const float* __restrict__ flw, const float* __restrict__ fbk,
       const float* __restrict__ bgate, float* __restrict__ out) {
    extern __shared__ float sm[];
    float* A_s = sm;                    // [64][ASTRIDE]
    float* B_s = sm + 64 * ASTRIDE;     // [32][BSTRIDE]

    const int b = blockIdx.y;
    const int px0 = blockIdx.x * 256;
    const int t = threadIdx.x;
    const int lane = t & 31;
    const int w = t >> 5;
    const int r2 = lane >> 2;   // 0..7
    const int r4 = lane & 3;    // 0..3

    // Stage A = M_b (already tf32-rounded)
    const float4* Mg = (const float4*)(g_M + b * 16384);
#pragma unroll
    for (int i = 0; i < 16; i++) {
        int idx4 = t + i * 256;
        int o = idx4 >> 6, kq = idx4 & 63;
        float4 v = Mg[idx4];
        *(float4*)(A_s + o * ASTRIDE + kq * 4) = v;
    }

    float acc[4][4][4];
#pragma unroll
    for (int mt = 0; mt < 4; mt++)
#pragma unroll
        for (int nf = 0; nf < 4; nf++)
#pragma unroll
            for (int q = 0; q < 4; q++) acc[mt][nf][q] = 0.f;

    const float* xp[4] = {low, high, flw, fbk};
    __syncthreads();

#pragma unroll 1
    for (int ch = 0; ch < 8; ch++) {
        const float* p = xp[ch >> 1] + (size_t)(b * 64 + (ch & 1) * 32) * HW + px0;
        // stage B chunk: 32 channels x 256 pixels, tf32-round on the fly
#pragma unroll
        for (int i = 0; i < 8; i++) {
            int idx4 = t + i * 256;
            int row = idx4 >> 6, col4 = idx4 & 63;
            float4 v = *(const float4*)(p + (size_t)row * HW + col4 * 4);
            float4 r;
            r.x = __uint_as_float(f2tf(v.x));
            r.y = __uint_as_float(f2tf(v.y));
            r.z = __uint_as_float(f2tf(v.z));
            r.w = __uint_as_float(f2tf(v.w));
            *(float4*)(B_s + row * BSTRIDE + col4 * 4) = r;
        }
        __syncthreads();

        const int k0g = ch * 32;
#pragma unroll
        for (int ks = 0; ks < 4; ks++) {
            const int kA = k0g + ks * 8;
            const int kB = ks * 8;
            uint32_t a[4][4];
#pragma unroll
            for (int mt = 0; mt < 4; mt++) {
                const float* ap = A_s + (mt * 16 + r2) * ASTRIDE + kA + r4;
                a[mt][0] = __float_as_uint(ap[0]);
                a[mt][1] = __float_as_uint(ap[8 * ASTRIDE]);
                a[mt][2] = __float_as_uint(ap[4]);
                a[mt][3] = __float_as_uint(ap[8 * ASTRIDE + 4]);
            }
#pragma unroll
            for (int nf = 0; nf < 4; nf++) {
                const float* bp = B_s + (kB + r4) * BSTRIDE + w * 32 + nf * 8 + r2;
                uint32_t b0 = __float_as_uint(bp[0]);
                uint32_t b1 = __float_as_uint(bp[4 * BSTRIDE]);
#pragma unroll
                for (int mt = 0; mt < 4; mt++)
                    mma_tf32(acc[mt][nf], a[mt][0], a[mt][1], a[mt][2], a[mt][3], b0, b1);
            }
        }
        __syncthreads();
    }

    // Epilogue: + bgate, write float2 (full 32B sectors per 4 lanes)
#pragma unroll
    for (int mt = 0; mt < 4; mt++) {
        int o_lo = mt * 16 + r2;
        int o_hi = o_lo + 8;
        float bgl = __ldg(bgate + o_lo);
        float bgh = __ldg(bgate + o_hi);
        float* olo = out + (size_t)(b * 64 + o_lo) * HW + px0 + w * 32 + 2 * r4;
        float* ohi = out + (size_t)(b * 64 + o_hi) * HW + px0 + w * 32 + 2 * r4;
#pragma unroll
        for (int nf = 0; nf < 4; nf++) {
            float2 v0 = {acc[mt][nf][0] + bgl, acc[mt][nf][1] + bgl};
            float2 v1 = {acc[mt][nf][2] + bgh, acc[mt][nf][3] + bgh};
            *(float2*)(olo + nf * 8) = v0;
            *(float2*)(ohi + nf * 8) = v1;
        }
    }
}

// ---------------------------------------------------------------------------
extern "C" void kernel_launch(void* const* d_in, const int* in_sizes, int n_in,
                              void* d_out, int out_size) {
    const float* low   = (const float*)d_in[0];
    const float* high  = (const float*)d_in[1];
    const float* flw   = (const float*)d_in[2];
    const float* fbk   = (const float*)d_in[3];
    const float* Wgcn  = (const float*)d_in[4];
    const float* bgcn  = (const float*)d_in[5];
    const float* W1    = (const float*)d_in[6];
    const float* b1    = (const float*)d_in[7];
    const float* W2    = (const float*)d_in[8];
    const float* b2    = (const float*)d_in[9];
    const float* W3    = (const float*)d_in[10];
    const float* b3    = (const float*)d_in[11];
    const float* W4    = (const float*)d_in[12];
    const float* b4    = (const float*)d_in[13];
    const float* Wgate = (const float*)d_in[14];
    const float* bgate = (const float*)d_in[15];
    float* out = (float*)d_out;

    k_pool<<<4096, 256>>>(low, high, flw, fbk);
    k_prep<<<16, 256>>>(Wgcn, bgcn, W1, b1, W2, b2, W3, b3, W4, b4, Wgate);

    const int smem = (64 * ASTRIDE + 32 * BSTRIDE) * (int)sizeof(float);  // 100,352 B
    cudaFuncSetAttribute(k_main, cudaFuncAttributeMaxDynamicSharedMemorySize, smem);
    k_main<<<dim3(64, 16), 256, smem>>>(low, high, flw, fbk, bgate, out);
}

// round 3
// speedup vs baseline: 1.9943x; 1.9943x over previous
#include <cuda_runtime.h>
#include <cstdint>

#define HW 16384
#define NB 16
#define AST 260   // A smem row stride: 260 % 32 == 4 -> conflict-free frag loads
#define BST 136   // B smem row stride: 136 % 32 == 8 -> conflict-free frag loads
#define TN  128   // pixels per CTA

// Scratch (allocation-free rule: __device__ globals)
__device__ float g_fc[NB * 4 * 64];      // pooled means [b][k][c]
__device__ float g_M[NB * 64 * 256];     // per-batch fused matrix, tf32-rounded

__device__ __forceinline__ uint32_t f2tf(float f) {
    uint32_t r;
    asm("cvt.rna.tf32.f32 %0, %1;" : "=r"(r) : "f"(f));
    return r;
}

__device__ __forceinline__ void mma_tf32(float c[4],
                                         uint32_t a0, uint32_t a1, uint32_t a2, uint32_t a3,
                                         uint32_t b0, uint32_t b1) {
    asm volatile(
        "mma.sync.aligned.m16n8k8.row.col.f32.tf32.tf32.f32 "
        "{%0,%1,%2,%3},{%4,%5,%6,%7},{%8,%9},{%0,%1,%2,%3};"
        : "+f"(c[0]), "+f"(c[1]), "+f"(c[2]), "+f"(c[3])
        : "r"(a0), "r"(a1), "r"(a2), "r"(a3), "r"(b0), "r"(b1));
}

__device__ __forceinline__ void cp16(uint32_t smem, const void* gmem) {
    asm volatile("cp.async.cg.shared.global [%0], [%1], 16;" :: "r"(smem), "l"(gmem));
}
__device__ __forceinline__ void cp_commit() {
    asm volatile("cp.async.commit_group;");
}
__device__ __forceinline__ void cp_wait1() {
    asm volatile("cp.async.wait_group 1;");
}

// ---------------------------------------------------------------------------
// Kernel 1: adaptive-avg-pool(1). One CTA per (b,k,c) plane.  (79.9% DRAM-bound)
// ---------------------------------------------------------------------------
__global__ void k_pool(const float* __restrict__ low, const float* __restrict__ high,
                       const float* __restrict__ flw, const float* __restrict__ fbk) {
    int plane = blockIdx.x;          // 0..4095
    int b = plane >> 8;
    int k = (plane >> 6) & 3;
    int c = plane & 63;
    const float* src = (k == 0) ? low : (k == 1) ? high : (k == 2) ? flw : fbk;
    src += (size_t)(b * 64 + c) * HW;

    int t = threadIdx.x;
    float s = 0.f;
    const float4* src4 = (const float4*)src;
#pragma unroll
    for (int i = 0; i < 16; i++) {
        float4 v = src4[t + i * 256];
        s += (v.x + v.y) + (v.z + v.w);
    }
    __shared__ float red[8];
#pragma unroll
    for (int off = 16; off; off >>= 1) s += __shfl_down_sync(0xffffffffu, s, off);
    if ((t & 31) == 0) red[t >> 5] = s;
    __syncthreads();
    if (t < 8) {
        s = red[t];
        s += __shfl_down_sync(0xffu, s, 4);
        s += __shfl_down_sync(0xffu, s, 2);
        s += __shfl_down_sync(0xffu, s, 1);
        if (t == 0) g_fc[(b * 4 + k) * 64 + c] = s * (1.0f / HW);
    }
}

// ---------------------------------------------------------------------------
// Kernel 2: adjacency + GCN + SE heads -> fused per-batch matrix M_b.
// ---------------------------------------------------------------------------
__global__ void k_prep(const float* __restrict__ Wgcn, const float* __restrict__ bgcn,
                       const float* __restrict__ W1, const float* __restrict__ b1,
                       const float* __restrict__ W2, const float* __restrict__ b2,
                       const float* __restrict__ W3, const float* __restrict__ b3,
                       const float* __restrict__ W4, const float* __restrict__ b4,
                       const float* __restrict__ Wgate) {
    int b = blockIdx.x;
    int t = threadIdx.x;
    __shared__ float fc_s[256];
    __shared__ float dot_s[16];
    __shared__ float adj_s[16];
    __shared__ float xw_s[256];
    __shared__ float h_s[256];
    __shared__ float e_s[256];

    fc_s[t] = g_fc[b * 256 + t];
    __syncthreads();

    if (t < 16) {
        int i = t >> 2, j = t & 3;
        float d = 0.f;
#pragma unroll
        for (int c = 0; c < 64; c++) d += fc_s[i * 64 + c] * fc_s[j * 64 + c];
        dot_s[t] = d;
    }
    __syncthreads();
    if (t < 16) {
        int i = t >> 2, j = t & 3;
        adj_s[t] = dot_s[t] / (sqrtf(dot_s[i * 4 + i]) * sqrtf(dot_s[j * 4 + j]));
    }
    __syncthreads();
    {
        int j = t >> 6, d = t & 63;
        float a = 0.f;
#pragma unroll 8
        for (int c = 0; c < 64; c++) a += fc_s[j * 64 + c] * Wgcn[c * 64 + d];
        xw_s[t] = a;
    }
    __syncthreads();
    {
        int i = t >> 6, d = t & 63;
        float a = bgcn[d];
#pragma unroll
        for (int j = 0; j < 4; j++) a += adj_s[i * 4 + j] * xw_s[j * 64 + d];
        h_s[t] = fmaxf(a, 0.f);
    }
    __syncthreads();
    {
        int k = t >> 6, j = t & 63;
        const float* Wk = (k == 0) ? W1 : (k == 1) ? W2 : (k == 2) ? W3 : W4;
        const float* bk = (k == 0) ? b1 : (k == 1) ? b2 : (k == 2) ? b3 : b4;
        float a = bk[j];
#pragma unroll 8
        for (int d = 0; d < 256; d++) a += h_s[d] * Wk[j * 256 + d];
        e_s[t] = 1.0f / (1.0f + expf(-a));
    }
    __syncthreads();
    // M_b[o, k*64+c] = Gk[o,c] + e_{k+1}[c] * (Gsum[o,c] - Gk[o,c]); tf32-rounded
#pragma unroll
    for (int i = 0; i < 64; i++) {
        int idx = t + i * 256;
        int o = idx >> 8, call = idx & 255;
        int k = call >> 6, c = call & 63;
        float gk = Wgate[idx];
        float gsum = Wgate[o * 256 + c] + Wgate[o * 256 + 64 + c] +
                     Wgate[o * 256 + 128 + c] + Wgate[o * 256 + 192 + c];
        float m = gk + e_s[k * 64 + c] * (gsum - gk);
        g_M[b * 16384 + idx] = __uint_as_float(f2tf(m));
    }
}

// ---------------------------------------------------------------------------
// Kernel 3: out[b,:,px_tile] = M_b @ X via tf32 mma + bgate.
// CTA = (128-px tile, batch), 256 threads / 8 warps.
// Warp tile: m=32 (2 m16-tiles) x n=32 (4 n8-frags) -> 32 acc regs (no spill).
// B double-buffered via cp.async; A staged once via cp.async.
// ---------------------------------------------------------------------------
__global__ void __launch_bounds__(256, 2)
k_main(const float* __restrict__ low, const float* __restrict__ high,
       const float* __restrict__ flw, const float* __restrict__ fbk,
       const float* __restrict__ bgate, float* __restrict__ out) {
    extern __shared__ float sm[];
    float* A_s = sm;                     // [64][AST]
    float* B_s = sm + 64 * AST;          // 2 x [32][BST]

    const int b   = blockIdx.y;
    const int px0 = blockIdx.x * TN;
    const int t    = threadIdx.x;
    const int lane = t & 31;
    const int w    = t >> 5;
    const int r2 = lane >> 2;   // 0..7
    const int r4 = lane & 3;    // 0..3
    const int wm = w >> 2;      // 0..1  (m half)
    const int wn = w & 3;       // 0..3  (n quarter)

    const uint32_t sA = (uint32_t)__cvta_generic_to_shared(A_s);
    const uint32_t sB = (uint32_t)__cvta_generic_to_shared(B_s);

    const float* xp[4] = {low, high, flw, fbk};

    // Stage A (M_b, tf32-pre-rounded): 64 rows x 256 floats = 4096 16B segs
    {
        const float* Mg = g_M + b * 16384;
#pragma unroll
        for (int i = 0; i < 16; i++) {
            int idx = t + i * 256;
            int o = idx >> 6, seg = idx & 63;
            cp16(sA + (uint32_t)(o * AST + seg * 4) * 4, Mg + o * 256 + seg * 4);
        }
    }
    // Stage B chunk 0 into buffer 0 (same cp.async group as A)
    {
        const float* p = xp[0] + (size_t)(b * 64) * HW + px0;
#pragma unroll
        for (int i = 0; i < 4; i++) {
            int idx = t + i * 256;
            int row = idx >> 5, seg = idx & 31;
            cp16(sB + (uint32_t)(row * BST + seg * 4) * 4, p + (size_t)row * HW + seg * 4);
        }
    }
    cp_commit();

    float acc[2][4][4];
#pragma unroll
    for (int mt = 0; mt < 2; mt++)
#pragma unroll
        for (int nf = 0; nf < 4; nf++)
#pragma unroll
            for (int q = 0; q < 4; q++) acc[mt][nf][q] = 0.f;

#pragma unroll 1
    for (int ch = 0; ch < 8; ch++) {
        // Prefetch next chunk into alternate buffer
        if (ch < 7) {
            int nc = ch + 1;
            const float* p = xp[nc >> 1] + (size_t)(b * 64 + (nc & 1) * 32) * HW + px0;
            uint32_t dst = sB + (uint32_t)((nc & 1) * 32 * BST) * 4;
#pragma unroll
            for (int i = 0; i < 4; i++) {
                int idx = t + i * 256;
                int row = idx >> 5, seg = idx & 31;
                cp16(dst + (uint32_t)(row * BST + seg * 4) * 4, p + (size_t)row * HW + seg * 4);
            }
        }
        cp_commit();
        cp_wait1();          // current chunk (and A on ch==0) has landed
        __syncthreads();

        const float* Bb    = B_s + (ch & 1) * 32 * BST;
        const float* Abase = A_s + (wm * 32 + r2) * AST + ch * 32 + r4;
#pragma unroll
        for (int ks = 0; ks < 4; ks++) {
            const float* ap = Abase + ks * 8;
            uint32_t a0[4], a1[4];
            a0[0] = __float_as_uint(ap[0]);
            a0[1] = __float_as_uint(ap[8 * AST]);
            a0[2] = __float_as_uint(ap[4]);
            a0[3] = __float_as_uint(ap[8 * AST + 4]);
            a1[0] = __float_as_uint(ap[16 * AST]);
            a1[1] = __float_as_uint(ap[24 * AST]);
            a1[2] = __float_as_uint(ap[16 * AST + 4]);
            a1[3] = __float_as_uint(ap[24 * AST + 4]);
            const float* bbase = Bb + (ks * 8 + r4) * BST + wn * 32 + r2;
#pragma unroll
            for (int nf = 0; nf < 4; nf++) {
                uint32_t b0 = f2tf(bbase[nf * 8]);
                uint32_t b1 = f2tf(bbase[nf * 8 + 4 * BST]);
                mma_tf32(acc[0][nf], a0[0], a0[1], a0[2], a0[3], b0, b1);
                mma_tf32(acc[1][nf], a1[0], a1[1], a1[2], a1[3], b0, b1);
            }
        }
        __syncthreads();     // protect buffer (ch&1) before it is re-filled
    }

    // Epilogue: + bgate, float2 stores (full 32B sectors)
#pragma unroll
    for (int mt = 0; mt < 2; mt++) {
        int o_lo = wm * 32 + mt * 16 + r2;
        int o_hi = o_lo + 8;
        float bgl = __ldg(bgate + o_lo);
        float bgh = __ldg(bgate + o_hi);
        float* olo = out + (size_t)(b * 64 + o_lo) * HW + px0 + wn * 32 + 2 * r4;
        float* ohi = out + (size_t)(b * 64 + o_hi) * HW + px0 + wn * 32 + 2 * r4;
#pragma unroll
        for (int nf = 0; nf < 4; nf++) {
            float2 v0 = {acc[mt][nf][0] + bgl, acc[mt][nf][1] + bgl};
            float2 v1 = {acc[mt][nf][2] + bgh, acc[mt][nf][3] + bgh};
            *(float2*)(olo + nf * 8) = v0;
            *(float2*)(ohi + nf * 8) = v1;
        }
    }
}

// ---------------------------------------------------------------------------
extern "C" void kernel_launch(void* const* d_in, const int* in_sizes, int n_in,
                              void* d_out, int out_size) {
    const float* low   = (const float*)d_in[0];
    const float* high  = (const float*)d_in[1];
    const float* flw   = (const float*)d_in[2];
    const float* fbk   = (const float*)d_in[3];
    const float* Wgcn  = (const float*)d_in[4];
    const float* bgcn  = (const float*)d_in[5];
    const float* W1    = (const float*)d_in[6];
    const float* b1    = (const float*)d_in[7];
    const float* W2    = (const float*)d_in[8];
    const float* b2    = (const float*)d_in[9];
    const float* W3    = (const float*)d_in[10];
    const float* b3    = (const float*)d_in[11];
    const float* W4    = (const float*)d_in[12];
    const float* b4    = (const float*)d_in[13];
    const float* Wgate = (const float*)d_in[14];
    const float* bgate = (const float*)d_in[15];
    float* out = (float*)d_out;

    k_pool<<<4096, 256>>>(low, high, flw, fbk);
    k_prep<<<16, 256>>>(Wgcn, bgcn, W1, b1, W2, b2, W3, b3, W4, b4, Wgate);

    const int smem = (64 * AST + 2 * 32 * BST) * (int)sizeof(float);  // 101,376 B
    cudaFuncSetAttribute(k_main, cudaFuncAttributeMaxDynamicSharedMemorySize, smem);
    k_main<<<dim3(HW / TN, NB), 256, smem>>>(low, high, flw, fbk, bgate, out);
}

// round 5
// speedup vs baseline: 2.0982x; 1.0521x over previous
#include <cuda_runtime.h>
#include <cuda_fp16.h>
#include <cstdint>

#define HW 16384
#define NB 16
#define AST_H 264      // A smem row stride in halves: 528B row shift -> conflict-free frags
#define BST2  136      // B smem row stride in half2:  544B row shift -> conflict-free frags
#define TN    128      // pixels per CTA
#define A_BYTES (64 * AST_H * 2)      // 33792
#define BBUF2   (16 * BST2)           // half2 per B buffer (16 kp-rows)

// Scratch (allocation-free rule: __device__ globals)
__device__ float  g_fc[NB * 4 * 64];       // pooled means [b][k][c]
__device__ __half g_Mh[NB * 64 * 256];     // per-batch fused matrix, fp16

__device__ __forceinline__ void mma_f16(float c[4],
                                        uint32_t a0, uint32_t a1, uint32_t a2, uint32_t a3,
                                        uint32_t b0, uint32_t b1) {
    asm volatile(
        "mma.sync.aligned.m16n8k16.row.col.f32.f16.f16.f32 "
        "{%0,%1,%2,%3},{%4,%5,%6,%7},{%8,%9},{%0,%1,%2,%3};"
        : "+f"(c[0]), "+f"(c[1]), "+f"(c[2]), "+f"(c[3])
        : "r"(a0), "r"(a1), "r"(a2), "r"(a3), "r"(b0), "r"(b1));
}

__device__ __forceinline__ void cp16(uint32_t smem, const void* gmem) {
    asm volatile("cp.async.cg.shared.global [%0], [%1], 16;" :: "r"(smem), "l"(gmem));
}

// ---------------------------------------------------------------------------
// Kernel 1: adaptive-avg-pool(1). One CTA per (b,k,c) plane. (83% DRAM-bound)
// ---------------------------------------------------------------------------
__global__ void k_pool(const float* __restrict__ low, const float* __restrict__ high,
                       const float* __restrict__ flw, const float* __restrict__ fbk) {
    int plane = blockIdx.x;          // 0..4095
    int b = plane >> 8;
    int k = (plane >> 6) & 3;
    int c = plane & 63;
    const float* src = (k == 0) ? low : (k == 1) ? high : (k == 2) ? flw : fbk;
    src += (size_t)(b * 64 + c) * HW;

    int t = threadIdx.x;
    float s = 0.f;
    const float4* src4 = (const float4*)src;
#pragma unroll
    for (int i = 0; i < 16; i++) {
        float4 v = src4[t + i * 256];
        s += (v.x + v.y) + (v.z + v.w);
    }
    __shared__ float red[8];
#pragma unroll
    for (int off = 16; off; off >>= 1) s += __shfl_down_sync(0xffffffffu, s, off);
    if ((t & 31) == 0) red[t >> 5] = s;
    __syncthreads();
    if (t < 8) {
        s = red[t];
        s += __shfl_down_sync(0xffu, s, 4);
        s += __shfl_down_sync(0xffu, s, 2);
        s += __shfl_down_sync(0xffu, s, 1);
        if (t == 0) g_fc[(b * 4 + k) * 64 + c] = s * (1.0f / HW);
    }
}

// ---------------------------------------------------------------------------
// Kernel 2: adjacency + GCN + SE heads -> fused per-batch fp16 matrix M_b.
// ---------------------------------------------------------------------------
__global__ void k_prep(const float* __restrict__ Wgcn, const float* __restrict__ bgcn,
                       const float* __restrict__ W1, const float* __restrict__ b1,
                       const float* __restrict__ W2, const float* __restrict__ b2,
                       const float* __restrict__ W3, const float* __restrict__ b3,
                       const float* __restrict__ W4, const float* __restrict__ b4,
                       const float* __restrict__ Wgate) {
    int b = blockIdx.x;
    int t = threadIdx.x;
    __shared__ float fc_s[256];
    __shared__ float dot_s[16];
    __shared__ float adj_s[16];
    __shared__ float xw_s[256];
    __shared__ float h_s[256];
    __shared__ float e_s[256];

    fc_s[t] = g_fc[b * 256 + t];
    __syncthreads();

    if (t < 16) {
        int i = t >> 2, j = t & 3;
        float d = 0.f;
#pragma unroll
        for (int c = 0; c < 64; c++) d += fc_s[i * 64 + c] * fc_s[j * 64 + c];
        dot_s[t] = d;
    }
    __syncthreads();
    if (t < 16) {
        int i = t >> 2, j = t & 3;
        adj_s[t] = dot_s[t] / (sqrtf(dot_s[i * 4 + i]) * sqrtf(dot_s[j * 4 + j]));
    }
    __syncthreads();
    {
        int j = t >> 6, d = t & 63;
        float a = 0.f;
#pragma unroll 8
        for (int c = 0; c < 64; c++) a += fc_s[j * 64 + c] * Wgcn[c * 64 + d];
        xw_s[t] = a;
    }
    __syncthreads();
    {
        int i = t >> 6, d = t & 63;
        float a = bgcn[d];
#pragma unroll
        for (int j = 0; j < 4; j++) a += adj_s[i * 4 + j] * xw_s[j * 64 + d];
        h_s[t] = fmaxf(a, 0.f);
    }
    __syncthreads();
    {
        int k = t >> 6, j = t & 63;
        const float* Wk = (k == 0) ? W1 : (k == 1) ? W2 : (k == 2) ? W3 : W4;
        const float* bk = (k == 0) ? b1 : (k == 1) ? b2 : (k == 2) ? b3 : b4;
        float a = bk[j];
#pragma unroll 8
        for (int d = 0; d < 256; d++) a += h_s[d] * Wk[j * 256 + d];
        e_s[t] = 1.0f / (1.0f + expf(-a));
    }
    __syncthreads();
    // M_b[o, k*64+c] = Gk[o,c] + e_{k+1}[c] * (Gsum[o,c] - Gk[o,c]); fp16-rounded
#pragma unroll
    for (int i = 0; i < 64; i++) {
        int idx = t + i * 256;
        int o = idx >> 8, call = idx & 255;
        int k = call >> 6, c = call & 63;
        float gk = Wgate[idx];
        float gsum = Wgate[o * 256 + c] + Wgate[o * 256 + 64 + c] +
                     Wgate[o * 256 + 128 + c] + Wgate[o * 256 + 192 + c];
        float m = gk + e_s[k * 64 + c] * (gsum - gk);
        g_Mh[b * 16384 + idx] = __float2half_rn(m);
    }
}

// ---------------------------------------------------------------------------
// Kernel 3: out[b,:,px_tile] = M_b @ X via fp16 mma (fp32 accum) + bgate.
// CTA = (128-px tile, batch), 256 threads / 8 warps.
// Warp tile m=32 x n=32. A: cp.async halves. B: LDG.128 pairs -> half2 k-pack
// -> STS.128, double-buffered.
// ---------------------------------------------------------------------------
__global__ void __launch_bounds__(256, 2)
k_main(const float* __restrict__ low, const float* __restrict__ high,
       const float* __restrict__ flw, const float* __restrict__ fbk,
       const float* __restrict__ bgate, float* __restrict__ out) {
    extern __shared__ char smc[];
    __half*  A_h = (__half*)smc;                    // [64][AST_H] halves
    __half2* B_2 = (__half2*)(smc + A_BYTES);       // 2 x [16 kp][BST2] half2

    const int b   = blockIdx.y;
    const int px0 = blockIdx.x * TN;
    const int t    = threadIdx.x;
    const int lane = t & 31;
    const int w    = t >> 5;
    const int r2 = lane >> 2;   // 0..7
    const int r4 = lane & 3;    // 0..3
    const int wm = w >> 2;      // 0..1  (m half)
    const int wn = w & 3;       // 0..3  (n quarter)

    const uint32_t sA = (uint32_t)__cvta_generic_to_shared(A_h);
    const float* xp[4] = {low, high, flw, fbk};

    // Stage A (M_b fp16): 64 rows x 256 halves = 2048 x 16B segments (8 iters!)
    {
        const __half* Mg = g_Mh + b * 16384;
#pragma unroll
        for (int i = 0; i < 8; i++) {
            int idx = t + i * 256;             // 0..2047
            int o = idx >> 5, seg = idx & 31;  // o: 0..63, seg: 0..31
            cp16(sA + (uint32_t)(o * AST_H + seg * 8) * 2, Mg + o * 256 + seg * 8);
        }
        asm volatile("cp.async.commit_group;");
    }

    // Prefetch B chunk 0 into registers (2 k-row pairs per thread)
    const int kp_t = t >> 5;        // this thread's kp for j=0 (j=1: +8)
    const int q_t  = t & 31;        // px quad
    float4 pa[2], pb[2];
    {
        const float* p = xp[0] + (size_t)(b * 64) * HW + px0;
#pragma unroll
        for (int j = 0; j < 2; j++) {
            int kp = kp_t + j * 8;
            pa[j] = *(const float4*)(p + (size_t)(2 * kp) * HW + q_t * 4);
            pb[j] = *(const float4*)(p + (size_t)(2 * kp + 1) * HW + q_t * 4);
        }
    }

    float acc[2][4][4];
#pragma unroll
    for (int mt = 0; mt < 2; mt++)
#pragma unroll
        for (int nf = 0; nf < 4; nf++)
#pragma unroll
            for (int q = 0; q < 4; q++) acc[mt][nf][q] = 0.f;

#pragma unroll 1
    for (int ch = 0; ch < 8; ch++) {
        // Pack current chunk into half2 tile [kp][n] (k-pairs in .lo/.hi)
        __half2* dst = B_2 + (ch & 1) * BBUF2;
#pragma unroll
        for (int j = 0; j < 2; j++) {
            int kp = kp_t + j * 8;
            __half2 h0 = __floats2half2_rn(pa[j].x, pb[j].x);
            __half2 h1 = __floats2half2_rn(pa[j].y, pb[j].y);
            __half2 h2 = __floats2half2_rn(pa[j].z, pb[j].z);
            __half2 h3 = __floats2half2_rn(pa[j].w, pb[j].w);
            __half2* d = dst + kp * BST2 + q_t * 4;
            uint4 pk;
            pk.x = *(uint32_t*)&h0; pk.y = *(uint32_t*)&h1;
            pk.z = *(uint32_t*)&h2; pk.w = *(uint32_t*)&h3;
            *(uint4*)d = pk;
        }
        // Prefetch next chunk (in flight during compute below)
        if (ch < 7) {
            int nc = ch + 1;
            const float* p = xp[nc >> 1] + (size_t)(b * 64 + (nc & 1) * 32) * HW + px0;
#pragma unroll
            for (int j = 0; j < 2; j++) {
                int kp = kp_t + j * 8;
                pa[j] = *(const float4*)(p + (size_t)(2 * kp) * HW + q_t * 4);
                pb[j] = *(const float4*)(p + (size_t)(2 * kp + 1) * HW + q_t * 4);
            }
        }
        if (ch == 0) asm volatile("cp.async.wait_group 0;");  // A landed
        __syncthreads();

        const __half2* Bb = B_2 + (ch & 1) * BBUF2;
        const __half*  Ab = A_h + (wm * 32 + r2) * AST_H + ch * 32 + 2 * r4;
#pragma unroll
        for (int ks = 0; ks < 2; ks++) {
            const __half* ap = Ab + ks * 16;
            uint32_t a0[4], a1[4];
            a0[0] = *(const uint32_t*)(ap);
            a0[1] = *(const uint32_t*)(ap + 8 * AST_H);
            a0[2] = *(const uint32_t*)(ap + 8);
            a0[3] = *(const uint32_t*)(ap + 8 * AST_H + 8);
            a1[0] = *(const uint32_t*)(ap + 16 * AST_H);
            a1[1] = *(const uint32_t*)(ap + 24 * AST_H);
            a1[2] = *(const uint32_t*)(ap + 16 * AST_H + 8);
            a1[3] = *(const uint32_t*)(ap + 24 * AST_H + 8);
            const __half2* bb = Bb + (ks * 8 + r4) * BST2 + wn * 32 + r2;
#pragma unroll
            for (int nf = 0; nf < 4; nf++) {
                uint32_t b0 = *(const uint32_t*)(bb + nf * 8);
                uint32_t b1 = *(const uint32_t*)(bb + nf * 8 + 4 * BST2);
                mma_f16(acc[0][nf], a0[0], a0[1], a0[2], a0[3], b0, b1);
                mma_f16(acc[1][nf], a1[0], a1[1], a1[2], a1[3], b0, b1);
            }
        }
        __syncthreads();     // protect buffer (ch&1) before re-fill
    }

    // Epilogue: + bgate, float2 stores (full 32B sectors)
#pragma unroll
    for (int mt = 0; mt < 2; mt++) {
        int o_lo = wm * 32 + mt * 16 + r2;
        int o_hi = o_lo + 8;
        float bgl = __ldg(bgate + o_lo);
        float bgh = __ldg(bgate + o_hi);
        float* olo = out + (size_t)(b * 64 + o_lo) * HW + px0 + wn * 32 + 2 * r4;
        float* ohi = out + (size_t)(b * 64 + o_hi) * HW + px0 + wn * 32 + 2 * r4;
#pragma unroll
        for (int nf = 0; nf < 4; nf++) {
            float2 v0 = {acc[mt][nf][0] + bgl, acc[mt][nf][1] + bgl};
            float2 v1 = {acc[mt][nf][2] + bgh, acc[mt][nf][3] + bgh};
            *(float2*)(olo + nf * 8) = v0;
            *(float2*)(ohi + nf * 8) = v1;
        }
    }
}

// ---------------------------------------------------------------------------
extern "C" void kernel_launch(void* const* d_in, const int* in_sizes, int n_in,
                              void* d_out, int out_size) {
    const float* low   = (const float*)d_in[0];
    const float* high  = (const float*)d_in[1];
    const float* flw   = (const float*)d_in[2];
    const float* fbk   = (const float*)d_in[3];
    const float* Wgcn  = (const float*)d_in[4];
    const float* bgcn  = (const float*)d_in[5];
    const float* W1    = (const float*)d_in[6];
    const float* b1    = (const float*)d_in[7];
    const float* W2    = (const float*)d_in[8];
    const float* b2    = (const float*)d_in[9];
    const float* W3    = (const float*)d_in[10];
    const float* b3    = (const float*)d_in[11];
    const float* W4    = (const float*)d_in[12];
    const float* b4    = (const float*)d_in[13];
    const float* Wgate = (const float*)d_in[14];
    const float* bgate = (const float*)d_in[15];
    float* out = (float*)d_out;

    k_pool<<<4096, 256>>>(low, high, flw, fbk);
    k_prep<<<16, 256>>>(Wgcn, bgcn, W1, b1, W2, b2, W3, b3, W4, b4, Wgate);

    const int smem = A_BYTES + 2 * BBUF2 * (int)sizeof(__half2);  // 51,200 B
    cudaFuncSetAttribute(k_main, cudaFuncAttributeMaxDynamicSharedMemorySize, smem);
    k_main<<<dim3(HW / TN, NB), 256, smem>>>(low, high, flw, fbk, bgate, out);
}

// round 6
// speedup vs baseline: 2.1508x; 1.0251x over previous
#include <cuda_runtime.h>
#include <cuda_fp16.h>
#include <cstdint>

#define HW 16384
#define NB 16
#define AST_H 264      // A smem row stride (halves): 528B/row -> 4-bank shift, conflict-free
#define BSTF  132      // B smem row stride (floats): 528B/row -> 4-bank shift, conflict-free
#define TN    128      // pixels per CTA
#define NST   6        // B pipeline stages (16 k-rows each)
#define A_BYTES (64 * AST_H * 2)      // 33792
#define STG_F   (16 * BSTF)           // floats per B stage

// Scratch (allocation-free rule: __device__ globals)
__device__ float  g_fc[NB * 4 * 64];       // pooled means [b][k][c]
__device__ __half g_Mh[NB * 64 * 256];     // per-batch fused matrix, fp16

__device__ __forceinline__ void mma_f16(float c[4],
                                        uint32_t a0, uint32_t a1, uint32_t a2, uint32_t a3,
                                        uint32_t b0, uint32_t b1) {
    asm volatile(
        "mma.sync.aligned.m16n8k16.row.col.f32.f16.f16.f32 "
        "{%0,%1,%2,%3},{%4,%5,%6,%7},{%8,%9},{%0,%1,%2,%3};"
        : "+f"(c[0]), "+f"(c[1]), "+f"(c[2]), "+f"(c[3])
        : "r"(a0), "r"(a1), "r"(a2), "r"(a3), "r"(b0), "r"(b1));
}

__device__ __forceinline__ void cp16(uint32_t smem, const void* gmem) {
    asm volatile("cp.async.cg.shared.global [%0], [%1], 16;" :: "r"(smem), "l"(gmem));
}
__device__ __forceinline__ void cp_commit() {
    asm volatile("cp.async.commit_group;");
}

// ---------------------------------------------------------------------------
// Kernel 1: adaptive-avg-pool(1). One CTA per (b,k,c) plane. (83% DRAM-bound)
// ---------------------------------------------------------------------------
__global__ void k_pool(const float* __restrict__ low, const float* __restrict__ high,
                       const float* __restrict__ flw, const float* __restrict__ fbk) {
    int plane = blockIdx.x;          // 0..4095
    int b = plane >> 8;
    int k = (plane >> 6) & 3;
    int c = plane & 63;
    const float* src = (k == 0) ? low : (k == 1) ? high : (k == 2) ? flw : fbk;
    src += (size_t)(b * 64 + c) * HW;

    int t = threadIdx.x;
    float s = 0.f;
    const float4* src4 = (const float4*)src;
#pragma unroll
    for (int i = 0; i < 16; i++) {
        float4 v = src4[t + i * 256];
        s += (v.x + v.y) + (v.z + v.w);
    }
    __shared__ float red[8];
#pragma unroll
    for (int off = 16; off; off >>= 1) s += __shfl_down_sync(0xffffffffu, s, off);
    if ((t & 31) == 0) red[t >> 5] = s;
    __syncthreads();
    if (t < 8) {
        s = red[t];
        s += __shfl_down_sync(0xffu, s, 4);
        s += __shfl_down_sync(0xffu, s, 2);
        s += __shfl_down_sync(0xffu, s, 1);
        if (t == 0) g_fc[(b * 4 + k) * 64 + c] = s * (1.0f / HW);
    }
}

// ---------------------------------------------------------------------------
// Kernel 2: adjacency + GCN + SE heads -> fused per-batch fp16 matrix M_b.
// ---------------------------------------------------------------------------
__global__ void k_prep(const float* __restrict__ Wgcn, const float* __restrict__ bgcn,
                       const float* __restrict__ W1, const float* __restrict__ b1,
                       const float* __restrict__ W2, const float* __restrict__ b2,
                       const float* __restrict__ W3, const float* __restrict__ b3,
                       const float* __restrict__ W4, const float* __restrict__ b4,
                       const float* __restrict__ Wgate) {
    int b = blockIdx.x;
    int t = threadIdx.x;
    __shared__ float fc_s[256];
    __shared__ float dot_s[16];
    __shared__ float adj_s[16];
    __shared__ float xw_s[256];
    __shared__ float h_s[256];
    __shared__ float e_s[256];

    fc_s[t] = g_fc[b * 256 + t];
    __syncthreads();

    if (t < 16) {
        int i = t >> 2, j = t & 3;
        float d = 0.f;
#pragma unroll
        for (int c = 0; c < 64; c++) d += fc_s[i * 64 + c] * fc_s[j * 64 + c];
        dot_s[t] = d;
    }
    __syncthreads();
    if (t < 16) {
        int i = t >> 2, j = t & 3;
        adj_s[t] = dot_s[t] / (sqrtf(dot_s[i * 4 + i]) * sqrtf(dot_s[j * 4 + j]));
    }
    __syncthreads();
    {
        int j = t >> 6, d = t & 63;
        float a = 0.f;
#pragma unroll 8
        for (int c = 0; c < 64; c++) a += fc_s[j * 64 + c] * Wgcn[c * 64 + d];
        xw_s[t] = a;
    }
    __syncthreads();
    {
        int i = t >> 6, d = t & 63;
        float a = bgcn[d];
#pragma unroll
        for (int j = 0; j < 4; j++) a += adj_s[i * 4 + j] * xw_s[j * 64 + d];
        h_s[t] = fmaxf(a, 0.f);
    }
    __syncthreads();
    {
        int k = t >> 6, j = t & 63;
        const float* Wk = (k == 0) ? W1 : (k == 1) ? W2 : (k == 2) ? W3 : W4;
        const float* bk = (k == 0) ? b1 : (k == 1) ? b2 : (k == 2) ? b3 : b4;
        float a = bk[j];
#pragma unroll 8
        for (int d = 0; d < 256; d++) a += h_s[d] * Wk[j * 256 + d];
        e_s[t] = 1.0f / (1.0f + expf(-a));
    }
    __syncthreads();
    // M_b[o, k*64+c] = Gk[o,c] + e_{k+1}[c] * (Gsum[o,c] - Gk[o,c]); fp16-rounded
#pragma unroll
    for (int i = 0; i < 64; i++) {
        int idx = t + i * 256;
        int o = idx >> 8, call = idx & 255;
        int k = call >> 6, c = call & 63;
        float gk = Wgate[idx];
        float gsum = Wgate[o * 256 + c] + Wgate[o * 256 + 64 + c] +
                     Wgate[o * 256 + 128 + c] + Wgate[o * 256 + 192 + c];
        float m = gk + e_s[k * 64 + c] * (gsum - gk);
        g_Mh[b * 16384 + idx] = __float2half_rn(m);
    }
}

// ---------------------------------------------------------------------------
// Kernel 3: out[b,:,px_tile] = M_b @ X via fp16 mma (fp32 accum) + bgate.
// CTA = (128-px tile, batch), 256 threads / 8 warps; warp tile m=32 x n=32.
// B: 6-stage cp.async ring of FLOAT stages (16 k-rows x 128 px), converted
// to half2 at frag-load time (single F2FP). One __syncthreads per stage.
// ---------------------------------------------------------------------------
__global__ void __launch_bounds__(256, 2)
k_main(const float* __restrict__ low, const float* __restrict__ high,
       const float* __restrict__ flw, const float* __restrict__ fbk,
       const float* __restrict__ bgate, float* __restrict__ out) {
    extern __shared__ char smc[];
    __half* A_h = (__half*)smc;                    // [64][AST_H] halves
    float*  B_f = (float*)(smc + A_BYTES);         // NST x [16][BSTF] floats

    const int b   = blockIdx.y;
    const int px0 = blockIdx.x * TN;
    const int t    = threadIdx.x;
    const int lane = t & 31;
    const int w    = t >> 5;
    const int r2 = lane >> 2;   // 0..7
    const int r4 = lane & 3;    // 0..3
    const int wm = w >> 2;      // 0..1  (m half)
    const int wn = w & 3;       // 0..3  (n quarter)

    const uint32_t sA = (uint32_t)__cvta_generic_to_shared(A_h);
    const uint32_t sB = (uint32_t)__cvta_generic_to_shared(B_f);
    const float* xp[4] = {low, high, flw, fbk};

    // Per-thread staging coords: 512 16B-segments per stage, 2 per thread.
    const int row0 = t >> 5;           // k-row for i=0 (i=1: +8)
    const int seg0 = t & 31;           // 16B segment within row

    // Issue stage s (s = 0..15): 16 k-rows of array s>>2, channel base (s&3)*16.
    auto issue_stage = [&](int s) {
        const float* base = xp[s >> 2] + (size_t)(b * 64 + (s & 3) * 16) * HW + px0;
        uint32_t dst = sB + (uint32_t)((s % NST) * STG_F) * 4;
#pragma unroll
        for (int i = 0; i < 2; i++) {
            int row = row0 + i * 8;
            cp16(dst + (uint32_t)(row * BSTF + seg0 * 4) * 4,
                 base + (size_t)row * HW + seg0 * 4);
        }
    };

    // Prologue: group0 = A + stage0; groups 1..4 = stages 1..4.
    {
        const __half* Mg = g_Mh + b * 16384;
#pragma unroll
        for (int i = 0; i < 8; i++) {
            int idx = t + i * 256;             // 0..2047
            int o = idx >> 5, seg = idx & 31;
            cp16(sA + (uint32_t)(o * AST_H + seg * 8) * 2, Mg + o * 256 + seg * 8);
        }
        issue_stage(0);
        cp_commit();
        issue_stage(1); cp_commit();
        issue_stage(2); cp_commit();
        issue_stage(3); cp_commit();
        issue_stage(4); cp_commit();
    }

    float acc[2][4][4];
#pragma unroll
    for (int mt = 0; mt < 2; mt++)
#pragma unroll
        for (int nf = 0; nf < 4; nf++)
#pragma unroll
            for (int q = 0; q < 4; q++) acc[mt][nf][q] = 0.f;

#pragma unroll 1
    for (int s = 0; s < 16; s++) {
        asm volatile("cp.async.wait_group 4;");   // stage s landed (uniform ledger)
        __syncthreads();                          // all warps done with stage s-1's buffer reuse target
        if (s + 5 < 16) issue_stage(s + 5);       // refill buffer (s+5)%6 == (s-1)%6
        cp_commit();                              // always: keep group count uniform

        const float* Bb = B_f + (s % NST) * STG_F;
        const __half* ap = A_h + (wm * 32 + r2) * AST_H + s * 16 + 2 * r4;
        uint32_t a0[4], a1[4];
        a0[0] = *(const uint32_t*)(ap);
        a0[1] = *(const uint32_t*)(ap + 8 * AST_H);
        a0[2] = *(const uint32_t*)(ap + 8);
        a0[3] = *(const uint32_t*)(ap + 8 * AST_H + 8);
        a1[0] = *(const uint32_t*)(ap + 16 * AST_H);
        a1[1] = *(const uint32_t*)(ap + 24 * AST_H);
        a1[2] = *(const uint32_t*)(ap + 16 * AST_H + 8);
        a1[3] = *(const uint32_t*)(ap + 24 * AST_H + 8);

        const float* bp = Bb + 2 * r4 * BSTF + wn * 32 + r2;
#pragma unroll
        for (int nf = 0; nf < 4; nf++) {
            const float* q = bp + nf * 8;
            __half2 h0 = __floats2half2_rn(q[0], q[BSTF]);
            __half2 h1 = __floats2half2_rn(q[8 * BSTF], q[9 * BSTF]);
            uint32_t b0 = *(uint32_t*)&h0;
            uint32_t b1 = *(uint32_t*)&h1;
            mma_f16(acc[0][nf], a0[0], a0[1], a0[2], a0[3], b0, b1);
            mma_f16(acc[1][nf], a1[0], a1[1], a1[2], a1[3], b0, b1);
        }
    }

    // Epilogue: + bgate, float2 stores (full 32B sectors)
#pragma unroll
    for (int mt = 0; mt < 2; mt++) {
        int o_lo = wm * 32 + mt * 16 + r2;
        int o_hi = o_lo + 8;
        float bgl = __ldg(bgate + o_lo);
        float bgh = __ldg(bgate + o_hi);
        float* olo = out + (size_t)(b * 64 + o_lo) * HW + px0 + wn * 32 + 2 * r4;
        float* ohi = out + (size_t)(b * 64 + o_hi) * HW + px0 + wn * 32 + 2 * r4;
#pragma unroll
        for (int nf = 0; nf < 4; nf++) {
            float2 v0 = {acc[mt][nf][0] + bgl, acc[mt][nf][1] + bgl};
            float2 v1 = {acc[mt][nf][2] + bgh, acc[mt][nf][3] + bgh};
            *(float2*)(olo + nf * 8) = v0;
            *(float2*)(ohi + nf * 8) = v1;
        }
    }
}

// ---------------------------------------------------------------------------
extern "C" void kernel_launch(void* const* d_in, const int* in_sizes, int n_in,
                              void* d_out, int out_size) {
    const float* low   = (const float*)d_in[0];
    const float* high  = (const float*)d_in[1];
    const float* flw   = (const float*)d_in[2];
    const float* fbk   = (const float*)d_in[3];
    const float* Wgcn  = (const float*)d_in[4];
    const float* bgcn  = (const float*)d_in[5];
    const float* W1    = (const float*)d_in[6];
    const float* b1    = (const float*)d_in[7];
    const float* W2    = (const float*)d_in[8];
    const float* b2    = (const float*)d_in[9];
    const float* W3    = (const float*)d_in[10];
    const float* b3    = (const float*)d_in[11];
    const float* W4    = (const float*)d_in[12];
    const float* b4    = (const float*)d_in[13];
    const float* Wgate = (const float*)d_in[14];
    const float* bgate = (const float*)d_in[15];
    float* out = (float*)d_out;

    k_pool<<<4096, 256>>>(low, high, flw, fbk);
    k_prep<<<16, 256>>>(Wgcn, bgcn, W1, b1, W2, b2, W3, b3, W4, b4, Wgate);

    const int smem = A_BYTES + NST * STG_F * (int)sizeof(float);  // 84,480 B
    cudaFuncSetAttribute(k_main, cudaFuncAttributeMaxDynamicSharedMemorySize, smem);
    k_main<<<dim3(HW / TN, NB), 256, smem>>>(low, high, flw, fbk, bgate, out);
}